// round 5
// baseline (speedup 1.0000x reference)
#include <cuda_runtime.h>
#include <cuda_bf16.h>
#include <mma.h>

using namespace nvcuda;

// Problem shape (fixed by the dataset instance)
constexpr int B  = 256;
constexpr int S  = 128;
constexpr int H  = 768;
constexpr int D  = S * H;      // 98304
constexpr int NL = 2;

// GEMM tiling
constexpr int KC     = 64;          // K elems staged per iteration
constexpr int LDT    = 72;          // padded smem leading dim (bf16 elems)
constexpr int KSPLIT = 48;          // grid.z
constexpr int KITERS = D / KC / KSPLIT;   // 32

// Device scratch (allocation-free rule: __device__ globals)
__device__ __nv_bfloat16 g_sf[(size_t)B * D];
__device__ __nv_bfloat16 g_tf[(size_t)B * D];
__device__ float g_dot[B * B];
__device__ float g_s2[B];
__device__ float g_t2[B];
__device__ float g_acc;

__inline__ __device__ float block_reduce_sum(float v) {
    __shared__ float sm[32];
    for (int o = 16; o > 0; o >>= 1) v += __shfl_down_sync(0xffffffffu, v, o);
    int lane = threadIdx.x & 31, w = threadIdx.x >> 5;
    if (lane == 0) sm[w] = v;
    __syncthreads();
    int nw = (blockDim.x + 31) >> 5;
    if (w == 0) {
        v = (lane < nw) ? sm[lane] : 0.f;
        for (int o = 16; o > 0; o >>= 1) v += __shfl_down_sync(0xffffffffu, v, o);
    }
    __syncthreads();
    return v;  // valid on thread 0
}

__global__ void zero_kernel() {
    int idx = blockIdx.x * blockDim.x + threadIdx.x;
    if (idx < B * B) g_dot[idx] = 0.f;
    if (idx == 0) g_acc = 0.f;
}

// fp32 -> bf16 conversion + fused row norms (of the rounded values, self-consistent with the GEMM)
__global__ void convert_kernel(const float* __restrict__ t_feat,
                               const float* __restrict__ s_feat) {
    int row  = blockIdx.x;
    int is_t = blockIdx.y;
    const float4* src = (const float4*)((is_t ? t_feat : s_feat) + (size_t)row * D);
    __nv_bfloat162* dst = (__nv_bfloat162*)((is_t ? g_tf : g_sf) + (size_t)row * D);
    float acc = 0.f;
    for (int i = threadIdx.x; i < D / 4; i += blockDim.x) {
        float4 v = src[i];
        __nv_bfloat162 lo = __float22bfloat162_rn(make_float2(v.x, v.y));
        __nv_bfloat162 hi = __float22bfloat162_rn(make_float2(v.z, v.w));
        dst[i * 2]     = lo;
        dst[i * 2 + 1] = hi;
        float f0 = __bfloat162float(lo.x), f1 = __bfloat162float(lo.y);
        float f2 = __bfloat162float(hi.x), f3 = __bfloat162float(hi.y);
        acc += f0 * f0 + f1 * f1 + f2 * f2 + f3 * f3;
    }
    float tot = block_reduce_sum(acc);
    if (threadIdx.x == 0) {
        if (is_t) g_t2[row] = tot; else g_s2[row] = tot;
    }
}

// Split-K bf16 wmma GEMM: dot[i][j] += sum_k sf_bf[i][k] * tf_bf[j][k]
__global__ void __launch_bounds__(256) gemm_kernel() {
    __shared__ __nv_bfloat16 smA[128 * LDT];
    __shared__ __nv_bfloat16 smB[128 * LDT];
    __shared__ float stage[8][256];

    const int m0 = blockIdx.x * 128;
    const int n0 = blockIdx.y * 128;
    const int kbase = blockIdx.z * KITERS * KC;
    const int tid = threadIdx.x, warp = tid >> 5, lane = tid & 31;
    const int wm = warp & 3;   // 4 warps across M (32 rows each)
    const int wn = warp >> 2;  // 2 warps across N (64 cols each)

    wmma::fragment<wmma::accumulator, 16, 16, 16, float> acc[2][4];
#pragma unroll
    for (int i = 0; i < 2; i++)
#pragma unroll
        for (int j = 0; j < 4; j++) wmma::fill_fragment(acc[i][j], 0.f);

    for (int it = 0; it < KITERS; ++it) {
        const int k0 = kbase + it * KC;
        // stage 128x64 bf16 tiles of A (sf rows) and B (tf rows)
#pragma unroll
        for (int c = tid; c < 1024; c += 256) {
            int row = c >> 3, seg = c & 7;
            *(uint4*)&smA[row * LDT + seg * 8] =
                *(const uint4*)&g_sf[(size_t)(m0 + row) * D + k0 + seg * 8];
            *(uint4*)&smB[row * LDT + seg * 8] =
                *(const uint4*)&g_tf[(size_t)(n0 + row) * D + k0 + seg * 8];
        }
        __syncthreads();
#pragma unroll
        for (int kk = 0; kk < KC; kk += 16) {
            wmma::fragment<wmma::matrix_a, 16, 16, 16, __nv_bfloat16, wmma::row_major> af[2];
            wmma::fragment<wmma::matrix_b, 16, 16, 16, __nv_bfloat16, wmma::col_major> bf[4];
#pragma unroll
            for (int i = 0; i < 2; i++)
                wmma::load_matrix_sync(af[i], &smA[(wm * 32 + i * 16) * LDT + kk], LDT);
#pragma unroll
            for (int j = 0; j < 4; j++)
                wmma::load_matrix_sync(bf[j], &smB[(wn * 64 + j * 16) * LDT + kk], LDT);
#pragma unroll
            for (int i = 0; i < 2; i++)
#pragma unroll
                for (int j = 0; j < 4; j++)
                    wmma::mma_sync(acc[i][j], af[i], bf[j], acc[i][j]);
        }
        __syncthreads();
    }

    // epilogue: atomic accumulate split-K partials into g_dot
#pragma unroll
    for (int i = 0; i < 2; i++)
#pragma unroll
        for (int j = 0; j < 4; j++) {
            wmma::store_matrix_sync(stage[warp], acc[i][j], 16, wmma::mem_row_major);
            __syncwarp();
            int r0 = m0 + wm * 32 + i * 16;
            int c0 = n0 + wn * 64 + j * 16;
#pragma unroll
            for (int e = lane; e < 256; e += 32)
                atomicAdd(&g_dot[(r0 + (e >> 4)) * B + c0 + (e & 15)], stage[warp][e]);
            __syncwarp();
        }
}

// One block per row i: sq_ij = max(s2_i + t2_j - 2*dot_ij, 0) for same-label j, else +inf;
// take k smallest, accumulate sum into g_acc.
__global__ void topk_kernel(const int* __restrict__ labels, const int* __restrict__ kptr) {
    const int i = blockIdx.x, j = threadIdx.x;
    const int li = labels[i];   // int32 (JAX default x64-disabled)
    const int lj = labels[j];
    const float BIG = 3e38f;
    float v = BIG;
    if (li == lj)
        v = fmaxf(g_s2[i] + g_t2[j] - 2.f * g_dot[i * B + j], 0.f);

    int k = kptr ? kptr[0] : 5;
    if (k > B) k = B;
    if (k < 0) k = 0;

    __shared__ float red[256];
    __shared__ int winner;
    float ssum = 0.f;
    for (int r = 0; r < k; ++r) {
        red[j] = v;
        __syncthreads();
        for (int s = 128; s > 0; s >>= 1) {
            if (j < s) red[j] = fminf(red[j], red[j + s]);
            __syncthreads();
        }
        float mv = red[0];
        if (j == 0) winner = -1;
        __syncthreads();
        if (mv < 1e37f && v == mv) {
            if (atomicCAS(&winner, -1, j) == -1) v = BIG;  // remove exactly one instance
        }
        if (j == 0 && mv < 1e37f) ssum += mv;
        __syncthreads();
    }
    if (j == 0) atomicAdd(&g_acc, ssum);
}

// Tiny losses + final assembly (NL == 2 hardcoded)
__global__ void final_kernel(const float* __restrict__ t_logits,
                             const float* __restrict__ s_logits,
                             const int* __restrict__ labels,
                             const int* __restrict__ tptr,
                             float* __restrict__ out) {
    const int b = threadIdx.x;  // 256 threads
    const float T = tptr ? (float)tptr[0] : 4.f;

    float s0 = s_logits[2 * b], s1 = s_logits[2 * b + 1];
    float m = fmaxf(s0, s1);
    float lse = m + logf(expf(s0 - m) + expf(s1 - m));
    int lab = labels[b];        // int32
    float tr = lse - (lab ? s1 : s0);

    float t0 = t_logits[2 * b] / T, t1 = t_logits[2 * b + 1] / T;
    float mt = fmaxf(t0, t1);
    float e0 = expf(t0 - mt), e1 = expf(t1 - mt);
    float Z = e0 + e1;
    float p0 = e0 / Z, p1 = e1 / Z;
    float q0 = s0 / T, q1 = s1 / T;
    float mq = fmaxf(q0, q1);
    float lseq = mq + logf(expf(q0 - mq) + expf(q1 - mq));
    float soft = p0 * (logf(p0) - (q0 - lseq)) + p1 * (logf(p1) - (q1 - lseq));

    float trs = block_reduce_sum(tr);
    float sfs = block_reduce_sum(soft);
    if (b == 0) {
        out[0] = trs / (float)B;
        out[1] = sfs / (float)B * T * T;
        out[2] = g_acc / (float)D;
    }
}

extern "C" void kernel_launch(void* const* d_in, const int* in_sizes, int n_in,
                              void* d_out, int out_size) {
    const float* t_logits = (const float*)d_in[0];
    const float* s_logits = (const float*)d_in[1];
    const float* t_feat   = (const float*)d_in[2];
    const float* s_feat   = (const float*)d_in[3];
    const int*   labels   = (const int*)d_in[4];            // int32 (JAX x64 disabled)
    const int*   kptr     = (n_in > 5) ? (const int*)d_in[5] : nullptr;
    const int*   tptr     = (n_in > 6) ? (const int*)d_in[6] : nullptr;
    float* out = (float*)d_out;

    zero_kernel<<<256, 256>>>();
    convert_kernel<<<dim3(B, 2), 256>>>(t_feat, s_feat);
    gemm_kernel<<<dim3(2, 2, KSPLIT), 256>>>();
    topk_kernel<<<B, 256>>>(labels, kptr);
    final_kernel<<<1, 256>>>(t_logits, s_logits, labels, tptr, out);
}